// round 14
// baseline (speedup 1.0000x reference)
#include <cuda_runtime.h>
#include <cuda_fp16.h>
#include <math.h>
#include <stdint.h>

// ---------------- problem dims (fixed) ----------------
#define BSZ   8
#define LSEQ  4096
#define HDIM  1024
#define PDIM  512
#define MTOT  (BSZ * LSEQ)        // 32768
#define CHUNKL 128
#define NCHK  (LSEQ / CHUNKL)     // 32
#define NCHUNKS_TOT (BSZ * NCHK)  // 256

#define S1_SCALE 1024.0f
#define S1_INV   (1.0f / 1024.0f)

// ---------------- device scratch ----------------
__device__ float2 g_lbc   [PDIM];               // lambda_bar
__device__ float2 g_lb32c [PDIM];               // lambda_bar^32
__device__ float2 g_lb128c[PDIM];               // lambda_bar^128
__device__ float  g_fac   [2 * PDIM];
__device__ __half g_uh  [(size_t)MTOT * 1024];
__device__ __half g_w1h [(size_t)1024 * 1024];  // rows interleaved: 2p=Re, 2p+1=Im (scaled)
__device__ __half g_w2h [(size_t)1024 * 1024];  // cols interleaved: 2p=C_re, 2p+1=-C_im
__device__ __half g_xsh [(size_t)MTOT * 1024];  // final xs fp16 (unscaled)
__device__ float2 g_cs2 [NCHUNKS_TOT * PDIM];   // per-chunk inclusive carries (scaled)
__device__ int    g_flag[NCHUNKS_TOT * 8];      // lookback ready flags (per by,bx)
__device__ int    g_xcnt[NCHUNKS_TOT];          // xs-chunk completion counters (0..8)

// ---------------- PTX helpers ----------------
__device__ __forceinline__ uint32_t smem_u32(const void* p) {
    uint32_t a;
    asm("{ .reg .u64 t; cvta.to.shared.u64 t, %1; cvt.u32.u64 %0, t; }" : "=r"(a) : "l"(p));
    return a;
}
#define CP_ASYNC16(dst, src) \
    asm volatile("cp.async.cg.shared.global [%0], [%1], 16;" :: "r"(dst), "l"(src) : "memory")
#define CP_COMMIT() asm volatile("cp.async.commit_group;" ::: "memory")
#define CP_WAIT1()  asm volatile("cp.async.wait_group 1;" ::: "memory")

__device__ __forceinline__ void ldsm4(uint32_t* r, uint32_t addr) {
    asm volatile("ldmatrix.sync.aligned.m8n8.x4.shared.b16 {%0,%1,%2,%3}, [%4];"
                 : "=r"(r[0]), "=r"(r[1]), "=r"(r[2]), "=r"(r[3]) : "r"(addr));
}
__device__ __forceinline__ void mma16816(float* d, const uint32_t* a, uint32_t b0, uint32_t b1) {
    asm volatile("mma.sync.aligned.m16n8k16.row.col.f32.f16.f16.f32 "
                 "{%0,%1,%2,%3}, {%4,%5,%6,%7}, {%8,%9}, {%0,%1,%2,%3};"
                 : "+f"(d[0]), "+f"(d[1]), "+f"(d[2]), "+f"(d[3])
                 : "r"(a[0]), "r"(a[1]), "r"(a[2]), "r"(a[3]), "r"(b0), "r"(b1));
}
#define SWZ(x) ((x) ^ (((x) >> 3) & 0x70))

__device__ __forceinline__ float2 cmuladd(float2 a, float2 b, float2 c) {
    return make_float2(fmaf(a.x, b.x, fmaf(-a.y, b.y, c.x)),
                       fmaf(a.x, b.y, fmaf( a.y, b.x, c.y)));
}

// ---------------- param prep (also zeroes flags/counters) ----------------
__global__ void prep_lambda_kernel(const float* __restrict__ Lre,
                                   const float* __restrict__ Lim,
                                   const float* __restrict__ lstep)
{
    int t = blockIdx.x * blockDim.x + threadIdx.x;   // 0..511
    #pragma unroll
    for (int i = t; i < NCHUNKS_TOT * 8; i += 512) g_flag[i] = 0;
    if (t < NCHUNKS_TOT) g_xcnt[t] = 0;

    int p = t;
    if (p >= PDIM) return;
    double lr = fmin((double)Lre[p], -1e-4);
    double li = (double)Lim[p];
    double s  = exp((double)lstep[p]);
    double er = exp(lr * s), th = li * s;
    double lbre = er * cos(th), lbim = er * sin(th);
    double den = lr * lr + li * li;
    double gre = lbre - 1.0, gim = lbim;
    g_lbc[p] = make_float2((float)lbre, (float)lbim);
    g_fac[p]        = (float)((gre * lr + gim * li) / den);
    g_fac[PDIM + p] = (float)((gim * lr - gre * li) / den);
    double er32 = exp(32.0 * lr * s), th32 = 32.0 * li * s;
    g_lb32c[p] = make_float2((float)(er32 * cos(th32)), (float)(er32 * sin(th32)));
    double er128 = exp(128.0 * lr * s), th128 = 128.0 * li * s;
    g_lb128c[p] = make_float2((float)(er128 * cos(th128)), (float)(er128 * sin(th128)));
}

__global__ void split_u_kernel(const float* __restrict__ u)
{
    size_t idx = (size_t)blockIdx.x * blockDim.x + threadIdx.x;
    size_t r = idx >> 8;
    int c = (int)(idx & 255) * 4;
    float4 v = *(const float4*)(u + r * 1024 + c);
    __half* o = g_uh + r * 1024;
    *(__half2*)(o + c)     = __floats2half2_rn(v.x, v.y);
    *(__half2*)(o + c + 2) = __floats2half2_rn(v.z, v.w);
}

// merged W1 + W2 prep
__global__ void split_w_kernel(const float* __restrict__ Bp,  // (P,H,2)
                               const float* __restrict__ Cp)  // (H,P,2)
{
    int bid = blockIdx.x;
    if (bid < 2048) {
        int idx = bid * blockDim.x + threadIdx.x;
        int p = idx >> 10, h = idx & 1023;
        float b0 = Bp[p * 2048 + h * 2 + 0];
        float b1 = Bp[p * 2048 + h * 2 + 1];
        float fr = g_fac[p], fi = g_fac[PDIM + p];
        g_w1h[(size_t)(2 * p)     * 1024 + h] = __float2half_rn((fr * b0 - fi * b1) * S1_SCALE);
        g_w1h[(size_t)(2 * p + 1) * 1024 + h] = __float2half_rn((fr * b1 + fi * b0) * S1_SCALE);
    } else {
        int idx = (bid - 2048) * blockDim.x + threadIdx.x;
        int h = idx >> 9, p = idx & 511;
        g_w2h[(size_t)h * 1024 + 2 * p]     = __float2half_rn( Cp[h * 1024 + p * 2 + 0]);
        g_w2h[(size_t)h * 1024 + 2 * p + 1] = __float2half_rn(-Cp[h * 1024 + p * 2 + 1]);
    }
}

// ---------------- fused mega kernel: GEMM1(+scan) then GEMM2, one launch ----
// grid (8, 512): by<256 -> GEMM1 CTA (k-major chunk map, fused lookback scan)
//                by>=256 -> GEMM2 CTA (spins on xs-chunk counter, then GEMM + D*u)
// Forward progress relies on bid-order dispatch: every consumer bid > all its
// producer bids (same property the R12/R13 lookback chain already depends on).
#define STAGE_BYTES 32768
#define SMEM_SZ (3 * STAGE_BYTES)
#define NCH 16

__device__ __forceinline__ void load_chunk_async(
    const __half* __restrict__ A, const __half* __restrict__ B,
    int bm, int bn, int c, uint32_t sA, uint32_t sB, int tid)
{
    int col = c * 64;
    const char* Ag = (const char*)(A + (size_t)bm * 1024 + col);
    const char* Bg = (const char*)(B + (size_t)bn * 1024 + col);
    #pragma unroll
    for (int i = 0; i < 4; i++) {
        int idx = tid + (i << 8);
        int row = idx >> 3, ch = (idx & 7) << 4;
        CP_ASYNC16(sA + SWZ(row * 128 + ch), Ag + (size_t)row * 2048 + ch);
    }
    #pragma unroll
    for (int i = 0; i < 4; i++) {
        int idx = tid + (i << 8);
        int row = idx >> 3, ch = (idx & 7) << 4;
        CP_ASYNC16(sB + SWZ(row * 128 + ch), Bg + (size_t)row * 2048 + ch);
    }
}

__global__ void __launch_bounds__(256, 2)
gemm_mega(float* __restrict__ Cout, const float* __restrict__ Dv)
{
    extern __shared__ char smem[];
    const uint32_t sbase = smem_u32(smem);
    const int tid = threadIdx.x;
    const int lane = tid & 31, wid = tid >> 5;
    const int wm = wid & 3, wn = wid >> 2;   // 4 x 2 warp grid
    const int by = blockIdx.y;
    const int mode = (by >= 256);            // 0 = GEMM1+scan, 1 = GEMM2
    const int byy = by & 255;
    const int bq = byy & 7;                  // batch
    const int kq = byy >> 3;                 // chunk k (k-major dispatch)
    const int chunk = bq * NCHK + kq;        // b-major chunk id
    const int bm = chunk * 128;
    const int bn = blockIdx.x * 128;

    const __half* A  = mode ? g_xsh : g_uh;
    const __half* Bm = mode ? g_w2h : g_w1h;

    // GEMM2: wait until this chunk's xs is fully produced (8 producer CTAs)
    if (mode) {
        if (tid == 0) {
            volatile int* cnt = (volatile int*)&g_xcnt[chunk];
            while (*cnt < 8) { }
            __threadfence();
        }
        __syncthreads();
    }

    uint32_t sA[3], sB[3];
    #pragma unroll
    for (int s = 0; s < 3; s++) { sA[s] = sbase + s * STAGE_BYTES; sB[s] = sA[s] + 16384; }

    load_chunk_async(A, Bm, bm, bn, 0, sA[0], sB[0], tid); CP_COMMIT();
    load_chunk_async(A, Bm, bm, bn, 1, sA[1], sB[1], tid); CP_COMMIT();

    float acc[2][8][4];
    #pragma unroll
    for (int i = 0; i < 2; i++)
        #pragma unroll
        for (int j = 0; j < 8; j++)
            #pragma unroll
            for (int k = 0; k < 4; k++) acc[i][j][k] = 0.0f;

    const int arow = wm * 32 + (lane & 15);
    const int brow = wn * 64 + (lane & 15);
    const int khalf = (lane >> 4) * 16;

    #pragma unroll 1
    for (int c = 0; c < NCH; c++) {
        CP_WAIT1();
        __syncthreads();
        if (c + 2 < NCH)
            load_chunk_async(A, Bm, bm, bn, c + 2, sA[(c + 2) % 3], sB[(c + 2) % 3], tid);
        CP_COMMIT();

        const uint32_t a = sA[c % 3], b = sB[c % 3];
        #pragma unroll
        for (int ks = 0; ks < 4; ks++) {
            const int kb = ks * 32 + khalf;
            uint32_t af0[4], af1[4];
            ldsm4(af0, a + SWZ(arow * 128 + kb));
            ldsm4(af1, a + SWZ((arow + 16) * 128 + kb));
            #pragma unroll
            for (int np = 0; np < 4; np++) {
                uint32_t bf[4];
                ldsm4(bf, b + SWZ((brow + np * 16) * 128 + kb));
                mma16816(acc[0][np * 2 + 0], af0, bf[0], bf[2]);
                mma16816(acc[0][np * 2 + 1], af0, bf[1], bf[3]);
                mma16816(acc[1][np * 2 + 0], af1, bf[0], bf[2]);
                mma16816(acc[1][np * 2 + 1], af1, bf[1], bf[3]);
            }
        }
    }

    if (mode) {
        // GEMM2 epilogue: += D*u, fp32 out
        #pragma unroll
        for (int mt = 0; mt < 2; mt++) {
            #pragma unroll
            for (int nt = 0; nt < 8; nt++) {
                const int row = bm + wm * 32 + mt * 16 + (lane >> 2);
                const int col = bn + wn * 64 + nt * 8 + (lane & 3) * 2;
                float d0 = acc[mt][nt][0], d1 = acc[mt][nt][1];
                float d2 = acc[mt][nt][2], d3 = acc[mt][nt][3];
                float2 dv = *(const float2*)(Dv + col);
                float2 u0 = __half22float2(*(const __half2*)(g_uh + (size_t)row * 1024 + col));
                float2 u1 = __half22float2(*(const __half2*)(g_uh + (size_t)(row + 8) * 1024 + col));
                d0 = fmaf(dv.x, u0.x, d0); d1 = fmaf(dv.y, u0.y, d1);
                d2 = fmaf(dv.x, u1.x, d2); d3 = fmaf(dv.y, u1.y, d3);
                *(float2*)(Cout + (size_t)row * 1024 + col)       = make_float2(d0, d1);
                *(float2*)(Cout + (size_t)(row + 8) * 1024 + col) = make_float2(d2, d3);
            }
        }
    } else {
        // GEMM1 epilogue: fused scan (4-quarter local + decoupled lookback)
        __syncthreads();
        float*  st = (float*)smem;                              // [128][130]
        float2* qs = (float2*)(smem + 128 * 130 * 4);           // [4][64] quarter sums
        float2* qc = (float2*)(smem + 128 * 130 * 4 + 2048);    // [4][64] quarter carry-ins
        #pragma unroll
        for (int mt = 0; mt < 2; mt++) {
            #pragma unroll
            for (int nt = 0; nt < 8; nt++) {
                const int row = wm * 32 + mt * 16 + (lane >> 2);
                const int col = wn * 64 + nt * 8 + (lane & 3) * 2;
                *(float2*)&st[row * 130 + col]       = make_float2(acc[mt][nt][0], acc[mt][nt][1]);
                *(float2*)&st[(row + 8) * 130 + col] = make_float2(acc[mt][nt][2], acc[mt][nt][3]);
            }
        }
        __syncthreads();
        // Phase A: 256 threads — zero-init local scan of a 32-step quarter
        {
            const int s  = tid & 63;
            const int jq = tid >> 6;
            const int p  = (bn >> 1) + s;
            const float2 lb = g_lbc[p];
            float2 x = make_float2(0.0f, 0.0f);
            float* base = &st[(jq * 32) * 130 + 2 * s];
            #pragma unroll 4
            for (int l = 0; l < 32; l++) {
                float2 v = *(float2*)(base + l * 130);
                x = cmuladd(lb, x, v);
                *(float2*)(base + l * 130) = x;
            }
            qs[jq * 64 + s] = x;
        }
        __syncthreads();
        // Phase B: 64 threads — combine, lookback, publish, derive carry-ins
        if (tid < 64) {
            const int s = tid;
            const int p = (bn >> 1) + s;
            const float2 l32  = g_lb32c[p];
            const float2 l128 = g_lb128c[p];
            float2 q0 = qs[s], q1 = qs[64 + s], q2 = qs[128 + s], q3 = qs[192 + s];
            float2 D1 = q0;
            float2 D2 = cmuladd(l32, D1, q1);
            float2 D3 = cmuladd(l32, D2, q2);
            float2 T  = cmuladd(l32, D3, q3);
            float2 cin = make_float2(0.0f, 0.0f);
            if (kq != 0) {
                volatile int* fl = (volatile int*)&g_flag[(byy - 8) * 8 + blockIdx.x];
                while (*fl == 0) { }
                __threadfence();
                volatile float* cp = (volatile float*)&g_cs2[(size_t)(byy - 8) * PDIM + p];
                cin.x = cp[0]; cin.y = cp[1];
            }
            g_cs2[(size_t)byy * PDIM + p] = cmuladd(l128, cin, T);
            __threadfence();
            float2 C0 = cin;
            float2 C1 = cmuladd(l32, C0, q0);
            float2 C2 = cmuladd(l32, C1, q1);
            float2 C3 = cmuladd(l32, C2, q2);
            qc[s]       = C0;
            qc[64 + s]  = C1;
            qc[128 + s] = C2;
            qc[192 + s] = C3;
        }
        __syncthreads();
        if (tid == 0) *(volatile int*)&g_flag[byy * 8 + blockIdx.x] = 1;
        // Phase C: 256 threads — apply correction, write fp16 xs
        {
            const int s  = tid & 63;
            const int jq = tid >> 6;
            const int p  = (bn >> 1) + s;
            const float2 lb = g_lbc[p];
            float2 cq = qc[jq * 64 + s];
            float2 g = make_float2(lb.x * cq.x - lb.y * cq.y,
                                   lb.x * cq.y + lb.y * cq.x);
            const float* base = &st[(jq * 32) * 130 + 2 * s];
            __half* xout = g_xsh + (size_t)(bm + jq * 32) * 1024 + bn + 2 * s;
            #pragma unroll 4
            for (int l = 0; l < 32; l++) {
                float2 v = *(const float2*)(base + l * 130);
                *(__half2*)(xout + (size_t)l * 1024) =
                    __floats2half2_rn((v.x + g.x) * S1_INV, (v.y + g.y) * S1_INV);
                g = make_float2(lb.x * g.x - lb.y * g.y,
                                lb.x * g.y + lb.y * g.x);
            }
        }
        // signal xs-chunk completion (after ALL threads' stores)
        __syncthreads();
        if (tid == 0) {
            __threadfence();
            atomicAdd(&g_xcnt[chunk], 1);
        }
    }
}

// ---------------- launcher ----------------
extern "C" void kernel_launch(void* const* d_in, const int* in_sizes, int n_in,
                              void* d_out, int out_size)
{
    const float* u     = (const float*)d_in[0];
    const float* Lre   = (const float*)d_in[1];
    const float* Lim   = (const float*)d_in[2];
    const float* Bp    = (const float*)d_in[3];
    const float* Cp    = (const float*)d_in[4];
    const float* Dv    = (const float*)d_in[5];
    const float* lstep = (const float*)d_in[6];
    float* out = (float*)d_out;

    cudaFuncSetAttribute((const void*)gemm_mega,
                         cudaFuncAttributeMaxDynamicSharedMemorySize, SMEM_SZ);

    // launch order keeps gemm_mega at index 3 (ncu capture slot)
    prep_lambda_kernel<<<2, 256>>>(Lre, Lim, lstep);          // 0 (zeroes flags+counters)
    split_u_kernel<<<MTOT, 256>>>(u);                          // 1
    split_w_kernel<<<4096, 256>>>(Bp, Cp);                     // 2

    dim3 grid(8, 512);   // by<256: GEMM1+scan, by>=256: GEMM2
    gemm_mega<<<grid, 256, SMEM_SZ>>>(out, Dv);                // 3 <- profiled
}

// round 15
// speedup vs baseline: 1.0017x; 1.0017x over previous
#include <cuda_runtime.h>
#include <cuda_fp16.h>
#include <math.h>
#include <stdint.h>

// ---------------- problem dims (fixed) ----------------
#define BSZ   8
#define LSEQ  4096
#define HDIM  1024
#define PDIM  512
#define MTOT  (BSZ * LSEQ)        // 32768
#define CHUNKL 128
#define NCHK  (LSEQ / CHUNKL)     // 32
#define NCHUNKS_TOT (BSZ * NCHK)  // 256

#define S1_SCALE 1024.0f
#define S1_INV   (1.0f / 1024.0f)

// ---------------- device scratch ----------------
__device__ float2 g_lbc   [PDIM];               // lambda_bar
__device__ float2 g_lb32c [PDIM];               // lambda_bar^32
__device__ float2 g_lb128c[PDIM];               // lambda_bar^128
__device__ float  g_fac   [2 * PDIM];
__device__ __half g_uh  [(size_t)MTOT * 1024];
__device__ __half g_w1h [(size_t)1024 * 1024];  // rows interleaved: 2p=Re, 2p+1=Im (scaled)
__device__ __half g_w2h [(size_t)1024 * 1024];  // cols interleaved: 2p=C_re, 2p+1=-C_im
__device__ __half g_xsh [(size_t)MTOT * 1024];  // final xs fp16 (unscaled)
__device__ float2 g_cs2 [NCHUNKS_TOT * PDIM];   // per-chunk inclusive carries (scaled)
__device__ int    g_flag[NCHUNKS_TOT * 8];      // lookback ready flags (per by,bx)
__device__ int    g_xcnt[NCHUNKS_TOT];          // xs-chunk completion counters (0..8)

// ---------------- PTX helpers ----------------
__device__ __forceinline__ uint32_t smem_u32(const void* p) {
    uint32_t a;
    asm("{ .reg .u64 t; cvta.to.shared.u64 t, %1; cvt.u32.u64 %0, t; }" : "=r"(a) : "l"(p));
    return a;
}
#define CP_ASYNC16(dst, src) \
    asm volatile("cp.async.cg.shared.global [%0], [%1], 16;" :: "r"(dst), "l"(src) : "memory")
#define CP_COMMIT() asm volatile("cp.async.commit_group;" ::: "memory")
#define CP_WAIT1()  asm volatile("cp.async.wait_group 1;" ::: "memory")
#define NANOSLEEP(ns) asm volatile("nanosleep.u32 %0;" :: "r"((uint32_t)(ns)))

__device__ __forceinline__ void ldsm4(uint32_t* r, uint32_t addr) {
    asm volatile("ldmatrix.sync.aligned.m8n8.x4.shared.b16 {%0,%1,%2,%3}, [%4];"
                 : "=r"(r[0]), "=r"(r[1]), "=r"(r[2]), "=r"(r[3]) : "r"(addr));
}
__device__ __forceinline__ void mma16816(float* d, const uint32_t* a, uint32_t b0, uint32_t b1) {
    asm volatile("mma.sync.aligned.m16n8k16.row.col.f32.f16.f16.f32 "
                 "{%0,%1,%2,%3}, {%4,%5,%6,%7}, {%8,%9}, {%0,%1,%2,%3};"
                 : "+f"(d[0]), "+f"(d[1]), "+f"(d[2]), "+f"(d[3])
                 : "r"(a[0]), "r"(a[1]), "r"(a[2]), "r"(a[3]), "r"(b0), "r"(b1));
}
#define SWZ(x) ((x) ^ (((x) >> 3) & 0x70))

__device__ __forceinline__ float2 cmuladd(float2 a, float2 b, float2 c) {
    return make_float2(fmaf(a.x, b.x, fmaf(-a.y, b.y, c.x)),
                       fmaf(a.x, b.y, fmaf( a.y, b.x, c.y)));
}

// ---------------- param prep (also zeroes flags/counters) ----------------
__global__ void prep_lambda_kernel(const float* __restrict__ Lre,
                                   const float* __restrict__ Lim,
                                   const float* __restrict__ lstep)
{
    int t = blockIdx.x * blockDim.x + threadIdx.x;   // 0..511
    #pragma unroll
    for (int i = t; i < NCHUNKS_TOT * 8; i += 512) g_flag[i] = 0;
    if (t < NCHUNKS_TOT) g_xcnt[t] = 0;

    int p = t;
    if (p >= PDIM) return;
    double lr = fmin((double)Lre[p], -1e-4);
    double li = (double)Lim[p];
    double s  = exp((double)lstep[p]);
    double er = exp(lr * s), th = li * s;
    double lbre = er * cos(th), lbim = er * sin(th);
    double den = lr * lr + li * li;
    double gre = lbre - 1.0, gim = lbim;
    g_lbc[p] = make_float2((float)lbre, (float)lbim);
    g_fac[p]        = (float)((gre * lr + gim * li) / den);
    g_fac[PDIM + p] = (float)((gim * lr - gre * li) / den);
    double er32 = exp(32.0 * lr * s), th32 = 32.0 * li * s;
    g_lb32c[p] = make_float2((float)(er32 * cos(th32)), (float)(er32 * sin(th32)));
    double er128 = exp(128.0 * lr * s), th128 = 128.0 * li * s;
    g_lb128c[p] = make_float2((float)(er128 * cos(th128)), (float)(er128 * sin(th128)));
}

__global__ void split_u_kernel(const float* __restrict__ u)
{
    size_t idx = (size_t)blockIdx.x * blockDim.x + threadIdx.x;
    size_t r = idx >> 8;
    int c = (int)(idx & 255) * 4;
    float4 v = *(const float4*)(u + r * 1024 + c);
    __half* o = g_uh + r * 1024;
    *(__half2*)(o + c)     = __floats2half2_rn(v.x, v.y);
    *(__half2*)(o + c + 2) = __floats2half2_rn(v.z, v.w);
}

// merged W1 + W2 prep
__global__ void split_w_kernel(const float* __restrict__ Bp,  // (P,H,2)
                               const float* __restrict__ Cp)  // (H,P,2)
{
    int bid = blockIdx.x;
    if (bid < 2048) {
        int idx = bid * blockDim.x + threadIdx.x;
        int p = idx >> 10, h = idx & 1023;
        float b0 = Bp[p * 2048 + h * 2 + 0];
        float b1 = Bp[p * 2048 + h * 2 + 1];
        float fr = g_fac[p], fi = g_fac[PDIM + p];
        g_w1h[(size_t)(2 * p)     * 1024 + h] = __float2half_rn((fr * b0 - fi * b1) * S1_SCALE);
        g_w1h[(size_t)(2 * p + 1) * 1024 + h] = __float2half_rn((fr * b1 + fi * b0) * S1_SCALE);
    } else {
        int idx = (bid - 2048) * blockDim.x + threadIdx.x;
        int h = idx >> 9, p = idx & 511;
        g_w2h[(size_t)h * 1024 + 2 * p]     = __float2half_rn( Cp[h * 1024 + p * 2 + 0]);
        g_w2h[(size_t)h * 1024 + 2 * p + 1] = __float2half_rn(-Cp[h * 1024 + p * 2 + 1]);
    }
}

// ---------------- fused mega kernel: GEMM1(+scan) then GEMM2, one launch ----
// grid (8, 512): by<256 -> GEMM1 CTA (k-major chunk map, fused lookback scan)
//                by>=256 -> GEMM2 CTA (sleeps on xs-chunk counter, then GEMM + D*u)
// All polls use nanosleep backoff so waiting warps vacate the schedulers.
#define STAGE_BYTES 32768
#define SMEM_SZ (3 * STAGE_BYTES)
#define NCH 16

__device__ __forceinline__ void load_chunk_async(
    const __half* __restrict__ A, const __half* __restrict__ B,
    int bm, int bn, int c, uint32_t sA, uint32_t sB, int tid)
{
    int col = c * 64;
    const char* Ag = (const char*)(A + (size_t)bm * 1024 + col);
    const char* Bg = (const char*)(B + (size_t)bn * 1024 + col);
    #pragma unroll
    for (int i = 0; i < 4; i++) {
        int idx = tid + (i << 8);
        int row = idx >> 3, ch = (idx & 7) << 4;
        CP_ASYNC16(sA + SWZ(row * 128 + ch), Ag + (size_t)row * 2048 + ch);
    }
    #pragma unroll
    for (int i = 0; i < 4; i++) {
        int idx = tid + (i << 8);
        int row = idx >> 3, ch = (idx & 7) << 4;
        CP_ASYNC16(sB + SWZ(row * 128 + ch), Bg + (size_t)row * 2048 + ch);
    }
}

__global__ void __launch_bounds__(256, 2)
gemm_mega(float* __restrict__ Cout, const float* __restrict__ Dv)
{
    extern __shared__ char smem[];
    const uint32_t sbase = smem_u32(smem);
    const int tid = threadIdx.x;
    const int lane = tid & 31, wid = tid >> 5;
    const int wm = wid & 3, wn = wid >> 2;   // 4 x 2 warp grid
    const int by = blockIdx.y;
    const int mode = (by >= 256);            // 0 = GEMM1+scan, 1 = GEMM2
    const int byy = by & 255;
    const int bq = byy & 7;                  // batch
    const int kq = byy >> 3;                 // chunk k (k-major dispatch)
    const int chunk = bq * NCHK + kq;        // b-major chunk id
    const int bm = chunk * 128;
    const int bn = blockIdx.x * 128;

    const __half* A  = mode ? g_xsh : g_uh;
    const __half* Bm = mode ? g_w2h : g_w1h;

    // GEMM2: sleep until this chunk's xs is fully produced (8 producer CTAs)
    if (mode) {
        if (tid == 0) {
            volatile int* cnt = (volatile int*)&g_xcnt[chunk];
            while (*cnt < 8) { NANOSLEEP(1024); }
            __threadfence();
        }
        __syncthreads();
    }

    uint32_t sA[3], sB[3];
    #pragma unroll
    for (int s = 0; s < 3; s++) { sA[s] = sbase + s * STAGE_BYTES; sB[s] = sA[s] + 16384; }

    load_chunk_async(A, Bm, bm, bn, 0, sA[0], sB[0], tid); CP_COMMIT();
    load_chunk_async(A, Bm, bm, bn, 1, sA[1], sB[1], tid); CP_COMMIT();

    float acc[2][8][4];
    #pragma unroll
    for (int i = 0; i < 2; i++)
        #pragma unroll
        for (int j = 0; j < 8; j++)
            #pragma unroll
            for (int k = 0; k < 4; k++) acc[i][j][k] = 0.0f;

    const int arow = wm * 32 + (lane & 15);
    const int brow = wn * 64 + (lane & 15);
    const int khalf = (lane >> 4) * 16;

    #pragma unroll 1
    for (int c = 0; c < NCH; c++) {
        CP_WAIT1();
        __syncthreads();
        if (c + 2 < NCH)
            load_chunk_async(A, Bm, bm, bn, c + 2, sA[(c + 2) % 3], sB[(c + 2) % 3], tid);
        CP_COMMIT();

        const uint32_t a = sA[c % 3], b = sB[c % 3];
        #pragma unroll
        for (int ks = 0; ks < 4; ks++) {
            const int kb = ks * 32 + khalf;
            uint32_t af0[4], af1[4];
            ldsm4(af0, a + SWZ(arow * 128 + kb));
            ldsm4(af1, a + SWZ((arow + 16) * 128 + kb));
            #pragma unroll
            for (int np = 0; np < 4; np++) {
                uint32_t bf[4];
                ldsm4(bf, b + SWZ((brow + np * 16) * 128 + kb));
                mma16816(acc[0][np * 2 + 0], af0, bf[0], bf[2]);
                mma16816(acc[0][np * 2 + 1], af0, bf[1], bf[3]);
                mma16816(acc[1][np * 2 + 0], af1, bf[0], bf[2]);
                mma16816(acc[1][np * 2 + 1], af1, bf[1], bf[3]);
            }
        }
    }

    if (mode) {
        // GEMM2 epilogue: += D*u, fp32 out
        #pragma unroll
        for (int mt = 0; mt < 2; mt++) {
            #pragma unroll
            for (int nt = 0; nt < 8; nt++) {
                const int row = bm + wm * 32 + mt * 16 + (lane >> 2);
                const int col = bn + wn * 64 + nt * 8 + (lane & 3) * 2;
                float d0 = acc[mt][nt][0], d1 = acc[mt][nt][1];
                float d2 = acc[mt][nt][2], d3 = acc[mt][nt][3];
                float2 dv = *(const float2*)(Dv + col);
                float2 u0 = __half22float2(*(const __half2*)(g_uh + (size_t)row * 1024 + col));
                float2 u1 = __half22float2(*(const __half2*)(g_uh + (size_t)(row + 8) * 1024 + col));
                d0 = fmaf(dv.x, u0.x, d0); d1 = fmaf(dv.y, u0.y, d1);
                d2 = fmaf(dv.x, u1.x, d2); d3 = fmaf(dv.y, u1.y, d3);
                *(float2*)(Cout + (size_t)row * 1024 + col)       = make_float2(d0, d1);
                *(float2*)(Cout + (size_t)(row + 8) * 1024 + col) = make_float2(d2, d3);
            }
        }
    } else {
        // GEMM1 epilogue: fused scan (4-quarter local + decoupled lookback)
        __syncthreads();
        float*  st = (float*)smem;                              // [128][130]
        float2* qs = (float2*)(smem + 128 * 130 * 4);           // [4][64] quarter sums
        float2* qc = (float2*)(smem + 128 * 130 * 4 + 2048);    // [4][64] quarter carry-ins
        #pragma unroll
        for (int mt = 0; mt < 2; mt++) {
            #pragma unroll
            for (int nt = 0; nt < 8; nt++) {
                const int row = wm * 32 + mt * 16 + (lane >> 2);
                const int col = wn * 64 + nt * 8 + (lane & 3) * 2;
                *(float2*)&st[row * 130 + col]       = make_float2(acc[mt][nt][0], acc[mt][nt][1]);
                *(float2*)&st[(row + 8) * 130 + col] = make_float2(acc[mt][nt][2], acc[mt][nt][3]);
            }
        }
        __syncthreads();
        // Phase A: 256 threads — zero-init local scan of a 32-step quarter
        {
            const int s  = tid & 63;
            const int jq = tid >> 6;
            const int p  = (bn >> 1) + s;
            const float2 lb = g_lbc[p];
            float2 x = make_float2(0.0f, 0.0f);
            float* base = &st[(jq * 32) * 130 + 2 * s];
            #pragma unroll 4
            for (int l = 0; l < 32; l++) {
                float2 v = *(float2*)(base + l * 130);
                x = cmuladd(lb, x, v);
                *(float2*)(base + l * 130) = x;
            }
            qs[jq * 64 + s] = x;
        }
        __syncthreads();
        // Phase B: 64 threads — combine, lookback, publish, derive carry-ins
        if (tid < 64) {
            const int s = tid;
            const int p = (bn >> 1) + s;
            const float2 l32  = g_lb32c[p];
            const float2 l128 = g_lb128c[p];
            float2 q0 = qs[s], q1 = qs[64 + s], q2 = qs[128 + s], q3 = qs[192 + s];
            float2 D1 = q0;
            float2 D2 = cmuladd(l32, D1, q1);
            float2 D3 = cmuladd(l32, D2, q2);
            float2 T  = cmuladd(l32, D3, q3);
            float2 cin = make_float2(0.0f, 0.0f);
            if (kq != 0) {
                volatile int* fl = (volatile int*)&g_flag[(byy - 8) * 8 + blockIdx.x];
                while (*fl == 0) { NANOSLEEP(128); }
                __threadfence();
                volatile float* cp = (volatile float*)&g_cs2[(size_t)(byy - 8) * PDIM + p];
                cin.x = cp[0]; cin.y = cp[1];
            }
            g_cs2[(size_t)byy * PDIM + p] = cmuladd(l128, cin, T);
            __threadfence();
            float2 C0 = cin;
            float2 C1 = cmuladd(l32, C0, q0);
            float2 C2 = cmuladd(l32, C1, q1);
            float2 C3 = cmuladd(l32, C2, q2);
            qc[s]       = C0;
            qc[64 + s]  = C1;
            qc[128 + s] = C2;
            qc[192 + s] = C3;
        }
        __syncthreads();
        if (tid == 0) *(volatile int*)&g_flag[byy * 8 + blockIdx.x] = 1;
        // Phase C: 256 threads — apply correction, write fp16 xs
        {
            const int s  = tid & 63;
            const int jq = tid >> 6;
            const int p  = (bn >> 1) + s;
            const float2 lb = g_lbc[p];
            float2 cq = qc[jq * 64 + s];
            float2 g = make_float2(lb.x * cq.x - lb.y * cq.y,
                                   lb.x * cq.y + lb.y * cq.x);
            const float* base = &st[(jq * 32) * 130 + 2 * s];
            __half* xout = g_xsh + (size_t)(bm + jq * 32) * 1024 + bn + 2 * s;
            #pragma unroll 4
            for (int l = 0; l < 32; l++) {
                float2 v = *(const float2*)(base + l * 130);
                *(__half2*)(xout + (size_t)l * 1024) =
                    __floats2half2_rn((v.x + g.x) * S1_INV, (v.y + g.y) * S1_INV);
                g = make_float2(lb.x * g.x - lb.y * g.y,
                                lb.x * g.y + lb.y * g.x);
            }
        }
        // signal xs-chunk completion (after ALL threads' stores)
        __syncthreads();
        if (tid == 0) {
            __threadfence();
            atomicAdd(&g_xcnt[chunk], 1);
        }
    }
}

// ---------------- launcher ----------------
extern "C" void kernel_launch(void* const* d_in, const int* in_sizes, int n_in,
                              void* d_out, int out_size)
{
    const float* u     = (const float*)d_in[0];
    const float* Lre   = (const float*)d_in[1];
    const float* Lim   = (const float*)d_in[2];
    const float* Bp    = (const float*)d_in[3];
    const float* Cp    = (const float*)d_in[4];
    const float* Dv    = (const float*)d_in[5];
    const float* lstep = (const float*)d_in[6];
    float* out = (float*)d_out;

    cudaFuncSetAttribute((const void*)gemm_mega,
                         cudaFuncAttributeMaxDynamicSharedMemorySize, SMEM_SZ);

    // launch order keeps gemm_mega at index 3 (ncu capture slot)
    prep_lambda_kernel<<<2, 256>>>(Lre, Lim, lstep);          // 0 (zeroes flags+counters)
    split_u_kernel<<<MTOT, 256>>>(u);                          // 1
    split_w_kernel<<<4096, 256>>>(Bp, Cp);                     // 2

    dim3 grid(8, 512);   // by<256: GEMM1+scan, by>=256: GEMM2
    gemm_mega<<<grid, 256, SMEM_SZ>>>(out, Dv);                // 3 <- profiled
}

// round 16
// speedup vs baseline: 1.0819x; 1.0800x over previous
#include <cuda_runtime.h>
#include <cuda_fp16.h>
#include <math.h>
#include <stdint.h>

// ---------------- problem dims (fixed) ----------------
#define BSZ   8
#define LSEQ  4096
#define HDIM  1024
#define PDIM  512
#define MTOT  (BSZ * LSEQ)        // 32768
#define CHUNKL 128
#define NCHK  (LSEQ / CHUNKL)     // 32
#define NCHUNKS_TOT (BSZ * NCHK)  // 256

#define S1_SCALE 1024.0f
#define S1_INV   (1.0f / 1024.0f)

// ---------------- device scratch ----------------
__device__ float2 g_lbc   [PDIM];               // lambda_bar
__device__ float2 g_lb32c [PDIM];               // lambda_bar^32
__device__ float2 g_lb128c[PDIM];               // lambda_bar^128
__device__ float  g_fac   [2 * PDIM];
__device__ __half g_uh  [(size_t)MTOT * 1024];
__device__ __half g_w1h [(size_t)1024 * 1024];  // rows interleaved: 2p=Re, 2p+1=Im (scaled)
__device__ __half g_w2h [(size_t)1024 * 1024];  // cols interleaved: 2p=C_re, 2p+1=-C_im
__device__ __half g_xsh [(size_t)MTOT * 1024];  // final xs fp16 (unscaled)
__device__ float2 g_cs2 [NCHUNKS_TOT * PDIM];   // per-chunk inclusive carries (scaled)
__device__ int    g_flag[NCHUNKS_TOT * 8];      // lookback ready flags (per by,bx)

// ---------------- PTX helpers ----------------
__device__ __forceinline__ uint32_t smem_u32(const void* p) {
    uint32_t a;
    asm("{ .reg .u64 t; cvta.to.shared.u64 t, %1; cvt.u32.u64 %0, t; }" : "=r"(a) : "l"(p));
    return a;
}
#define CP_ASYNC16(dst, src) \
    asm volatile("cp.async.cg.shared.global [%0], [%1], 16;" :: "r"(dst), "l"(src) : "memory")
#define CP_COMMIT() asm volatile("cp.async.commit_group;" ::: "memory")
#define CP_WAIT1()  asm volatile("cp.async.wait_group 1;" ::: "memory")

__device__ __forceinline__ void ldsm4(uint32_t* r, uint32_t addr) {
    asm volatile("ldmatrix.sync.aligned.m8n8.x4.shared.b16 {%0,%1,%2,%3}, [%4];"
                 : "=r"(r[0]), "=r"(r[1]), "=r"(r[2]), "=r"(r[3]) : "r"(addr));
}
__device__ __forceinline__ void mma16816(float* d, const uint32_t* a, uint32_t b0, uint32_t b1) {
    asm volatile("mma.sync.aligned.m16n8k16.row.col.f32.f16.f16.f32 "
                 "{%0,%1,%2,%3}, {%4,%5,%6,%7}, {%8,%9}, {%0,%1,%2,%3};"
                 : "+f"(d[0]), "+f"(d[1]), "+f"(d[2]), "+f"(d[3])
                 : "r"(a[0]), "r"(a[1]), "r"(a[2]), "r"(a[3]), "r"(b0), "r"(b1));
}
#define SWZ(x) ((x) ^ (((x) >> 3) & 0x70))

__device__ __forceinline__ float2 cmuladd(float2 a, float2 b, float2 c) {
    return make_float2(fmaf(a.x, b.x, fmaf(-a.y, b.y, c.x)),
                       fmaf(a.x, b.y, fmaf( a.y, b.x, c.y)));
}

// ---------------- param prep (also zeroes lookback flags) ----------------
__global__ void prep_lambda_kernel(const float* __restrict__ Lre,
                                   const float* __restrict__ Lim,
                                   const float* __restrict__ lstep)
{
    int t = blockIdx.x * blockDim.x + threadIdx.x;   // 0..511
    #pragma unroll
    for (int i = t; i < NCHUNKS_TOT * 8; i += 512) g_flag[i] = 0;

    int p = t;
    if (p >= PDIM) return;
    double lr = fmin((double)Lre[p], -1e-4);
    double li = (double)Lim[p];
    double s  = exp((double)lstep[p]);
    double er = exp(lr * s), th = li * s;
    double lbre = er * cos(th), lbim = er * sin(th);
    double den = lr * lr + li * li;
    double gre = lbre - 1.0, gim = lbim;
    g_lbc[p] = make_float2((float)lbre, (float)lbim);
    g_fac[p]        = (float)((gre * lr + gim * li) / den);
    g_fac[PDIM + p] = (float)((gim * lr - gre * li) / den);
    double er32 = exp(32.0 * lr * s), th32 = 32.0 * li * s;
    g_lb32c[p] = make_float2((float)(er32 * cos(th32)), (float)(er32 * sin(th32)));
    double er128 = exp(128.0 * lr * s), th128 = 128.0 * li * s;
    g_lb128c[p] = make_float2((float)(er128 * cos(th128)), (float)(er128 * sin(th128)));
}

// ---------------- merged split kernel: u (fp32->fp16), W1, W2 ----------------
// blocks [0, 16384): u, 8 elems/thread
// blocks [16384, 18432): W1
// blocks [18432, 20480): W2
__global__ void split_all_kernel(const float* __restrict__ u,
                                 const float* __restrict__ Bp,   // (P,H,2)
                                 const float* __restrict__ Cp)   // (H,P,2)
{
    int bid = blockIdx.x;
    if (bid < 16384) {
        size_t base = ((size_t)bid * 256 + threadIdx.x) * 8;
        float4 v0 = *(const float4*)(u + base);
        float4 v1 = *(const float4*)(u + base + 4);
        __half* o = g_uh + base;
        *(__half2*)(o)     = __floats2half2_rn(v0.x, v0.y);
        *(__half2*)(o + 2) = __floats2half2_rn(v0.z, v0.w);
        *(__half2*)(o + 4) = __floats2half2_rn(v1.x, v1.y);
        *(__half2*)(o + 6) = __floats2half2_rn(v1.z, v1.w);
    } else if (bid < 18432) {
        int idx = (bid - 16384) * 256 + threadIdx.x;
        int p = idx >> 10, h = idx & 1023;
        float b0 = Bp[p * 2048 + h * 2 + 0];
        float b1 = Bp[p * 2048 + h * 2 + 1];
        float fr = g_fac[p], fi = g_fac[PDIM + p];
        g_w1h[(size_t)(2 * p)     * 1024 + h] = __float2half_rn((fr * b0 - fi * b1) * S1_SCALE);
        g_w1h[(size_t)(2 * p + 1) * 1024 + h] = __float2half_rn((fr * b1 + fi * b0) * S1_SCALE);
    } else {
        int idx = (bid - 18432) * 256 + threadIdx.x;
        int h = idx >> 9, p = idx & 511;
        g_w2h[(size_t)h * 1024 + 2 * p]     = __float2half_rn( Cp[h * 1024 + p * 2 + 0]);
        g_w2h[(size_t)h * 1024 + 2 * p + 1] = __float2half_rn(-Cp[h * 1024 + p * 2 + 1]);
    }
}

// ---------------- HMMA fp16 GEMM: C = A(Mx1024) * B(1024x1024)^T ----
// 256 threads, 4x2 warp grid, 32x64 warp tile (proven optimum).
// MODE 0 (GEMM1): epilogue = fused scan, 4-quarter parallel + decoupled lookback.
// MODE 1 (GEMM2): epilogue = += D * u, fp32 out.
#define STAGE_BYTES 32768
#define SMEM_SZ (3 * STAGE_BYTES)
#define NCH 16

__device__ __forceinline__ void load_chunk_async(
    const __half* __restrict__ A, const __half* __restrict__ B,
    int bm, int bn, int c, uint32_t sA, uint32_t sB, int tid)
{
    int col = c * 64;
    const char* Ag = (const char*)(A + (size_t)bm * 1024 + col);
    const char* Bg = (const char*)(B + (size_t)bn * 1024 + col);
    #pragma unroll
    for (int i = 0; i < 4; i++) {
        int idx = tid + (i << 8);
        int row = idx >> 3, ch = (idx & 7) << 4;
        CP_ASYNC16(sA + SWZ(row * 128 + ch), Ag + (size_t)row * 2048 + ch);
    }
    #pragma unroll
    for (int i = 0; i < 4; i++) {
        int idx = tid + (i << 8);
        int row = idx >> 3, ch = (idx & 7) << 4;
        CP_ASYNC16(sB + SWZ(row * 128 + ch), Bg + (size_t)row * 2048 + ch);
    }
}

template<int MODE>
__global__ void __launch_bounds__(256, 2)
gemm_mma(const __half* __restrict__ A, const __half* __restrict__ Bm,
         float* __restrict__ Cout, const float* __restrict__ Dv,
         const __half* __restrict__ Uh)
{
    extern __shared__ char smem[];
    const uint32_t sbase = smem_u32(smem);
    const int tid = threadIdx.x;
    const int lane = tid & 31, wid = tid >> 5;
    const int wm = wid & 3, wn = wid >> 2;   // 4 x 2 warp grid
    const int by = blockIdx.y;
    const int bq = by & 7;          // batch b  (MODE 0 k-major map)
    const int kq = by >> 3;         // chunk k
    const int bm = (MODE == 0) ? (bq * NCHK + kq) * 128 : by * 128;
    const int bn = blockIdx.x * 128;

    uint32_t sA[3], sB[3];
    #pragma unroll
    for (int s = 0; s < 3; s++) { sA[s] = sbase + s * STAGE_BYTES; sB[s] = sA[s] + 16384; }

    load_chunk_async(A, Bm, bm, bn, 0, sA[0], sB[0], tid); CP_COMMIT();
    load_chunk_async(A, Bm, bm, bn, 1, sA[1], sB[1], tid); CP_COMMIT();

    float acc[2][8][4];
    #pragma unroll
    for (int i = 0; i < 2; i++)
        #pragma unroll
        for (int j = 0; j < 8; j++)
            #pragma unroll
            for (int k = 0; k < 4; k++) acc[i][j][k] = 0.0f;

    const int arow = wm * 32 + (lane & 15);
    const int brow = wn * 64 + (lane & 15);
    const int khalf = (lane >> 4) * 16;

    #pragma unroll 1
    for (int c = 0; c < NCH; c++) {
        CP_WAIT1();
        __syncthreads();
        if (c + 2 < NCH)
            load_chunk_async(A, Bm, bm, bn, c + 2, sA[(c + 2) % 3], sB[(c + 2) % 3], tid);
        CP_COMMIT();

        const uint32_t a = sA[c % 3], b = sB[c % 3];
        #pragma unroll
        for (int ks = 0; ks < 4; ks++) {
            const int kb = ks * 32 + khalf;
            uint32_t af0[4], af1[4];
            ldsm4(af0, a + SWZ(arow * 128 + kb));
            ldsm4(af1, a + SWZ((arow + 16) * 128 + kb));
            #pragma unroll
            for (int np = 0; np < 4; np++) {
                uint32_t bf[4];
                ldsm4(bf, b + SWZ((brow + np * 16) * 128 + kb));
                mma16816(acc[0][np * 2 + 0], af0, bf[0], bf[2]);
                mma16816(acc[0][np * 2 + 1], af0, bf[1], bf[3]);
                mma16816(acc[1][np * 2 + 0], af1, bf[0], bf[2]);
                mma16816(acc[1][np * 2 + 1], af1, bf[1], bf[3]);
            }
        }
    }

    if (MODE == 1) {
        // epilogue: += D*u, fp32 out
        #pragma unroll
        for (int mt = 0; mt < 2; mt++) {
            #pragma unroll
            for (int nt = 0; nt < 8; nt++) {
                const int row = bm + wm * 32 + mt * 16 + (lane >> 2);
                const int col = bn + wn * 64 + nt * 8 + (lane & 3) * 2;
                float d0 = acc[mt][nt][0], d1 = acc[mt][nt][1];
                float d2 = acc[mt][nt][2], d3 = acc[mt][nt][3];
                float2 dv = *(const float2*)(Dv + col);
                float2 u0 = __half22float2(*(const __half2*)(Uh + (size_t)row * 1024 + col));
                float2 u1 = __half22float2(*(const __half2*)(Uh + (size_t)(row + 8) * 1024 + col));
                d0 = fmaf(dv.x, u0.x, d0); d1 = fmaf(dv.y, u0.y, d1);
                d2 = fmaf(dv.x, u1.x, d2); d3 = fmaf(dv.y, u1.y, d3);
                *(float2*)(Cout + (size_t)row * 1024 + col)       = make_float2(d0, d1);
                *(float2*)(Cout + (size_t)(row + 8) * 1024 + col) = make_float2(d2, d3);
            }
        }
    } else {
        // fused scan: 4-quarter parallel local scan + decoupled lookback
        __syncthreads();
        float*  st = (float*)smem;                              // [128][130]
        float2* qs = (float2*)(smem + 128 * 130 * 4);           // [4][64] quarter sums
        float2* qc = (float2*)(smem + 128 * 130 * 4 + 2048);    // [4][64] quarter carry-ins
        #pragma unroll
        for (int mt = 0; mt < 2; mt++) {
            #pragma unroll
            for (int nt = 0; nt < 8; nt++) {
                const int row = wm * 32 + mt * 16 + (lane >> 2);
                const int col = wn * 64 + nt * 8 + (lane & 3) * 2;
                *(float2*)&st[row * 130 + col]       = make_float2(acc[mt][nt][0], acc[mt][nt][1]);
                *(float2*)&st[(row + 8) * 130 + col] = make_float2(acc[mt][nt][2], acc[mt][nt][3]);
            }
        }
        __syncthreads();
        // Phase A: 256 threads — zero-init local scan of a 32-step quarter
        {
            const int s  = tid & 63;
            const int jq = tid >> 6;
            const int p  = (bn >> 1) + s;
            const float2 lb = g_lbc[p];
            float2 x = make_float2(0.0f, 0.0f);
            float* base = &st[(jq * 32) * 130 + 2 * s];
            #pragma unroll 4
            for (int l = 0; l < 32; l++) {
                float2 v = *(float2*)(base + l * 130);
                x = cmuladd(lb, x, v);
                *(float2*)(base + l * 130) = x;
            }
            qs[jq * 64 + s] = x;
        }
        __syncthreads();
        // Phase B: 64 threads — combine, lookback, publish, derive carry-ins
        if (tid < 64) {
            const int s = tid;
            const int p = (bn >> 1) + s;
            const float2 l32  = g_lb32c[p];
            const float2 l128 = g_lb128c[p];
            float2 q0 = qs[s], q1 = qs[64 + s], q2 = qs[128 + s], q3 = qs[192 + s];
            float2 D1 = q0;
            float2 D2 = cmuladd(l32, D1, q1);
            float2 D3 = cmuladd(l32, D2, q2);
            float2 T  = cmuladd(l32, D3, q3);
            float2 cin = make_float2(0.0f, 0.0f);
            if (kq != 0) {
                volatile int* fl = (volatile int*)&g_flag[(by - 8) * 8 + blockIdx.x];
                while (*fl == 0) { }
                __threadfence();
                volatile float* cp = (volatile float*)&g_cs2[(size_t)(by - 8) * PDIM + p];
                cin.x = cp[0]; cin.y = cp[1];
            }
            g_cs2[(size_t)by * PDIM + p] = cmuladd(l128, cin, T);
            __threadfence();
            float2 C0 = cin;
            float2 C1 = cmuladd(l32, C0, q0);
            float2 C2 = cmuladd(l32, C1, q1);
            float2 C3 = cmuladd(l32, C2, q2);
            qc[s]       = C0;
            qc[64 + s]  = C1;
            qc[128 + s] = C2;
            qc[192 + s] = C3;
        }
        __syncthreads();
        if (tid == 0) *(volatile int*)&g_flag[by * 8 + blockIdx.x] = 1;
        // Phase C: 256 threads — apply correction, write fp16 xs
        {
            const int s  = tid & 63;
            const int jq = tid >> 6;
            const int p  = (bn >> 1) + s;
            const float2 lb = g_lbc[p];
            float2 cq = qc[jq * 64 + s];
            float2 g = make_float2(lb.x * cq.x - lb.y * cq.y,
                                   lb.x * cq.y + lb.y * cq.x);
            const float* base = &st[(jq * 32) * 130 + 2 * s];
            __half* xout = g_xsh + (size_t)(bm + jq * 32) * 1024 + bn + 2 * s;
            #pragma unroll 4
            for (int l = 0; l < 32; l++) {
                float2 v = *(const float2*)(base + l * 130);
                *(__half2*)(xout + (size_t)l * 1024) =
                    __floats2half2_rn((v.x + g.x) * S1_INV, (v.y + g.y) * S1_INV);
                g = make_float2(lb.x * g.x - lb.y * g.y,
                                lb.x * g.y + lb.y * g.x);
            }
        }
    }
}

// ---------------- launcher ----------------
extern "C" void kernel_launch(void* const* d_in, const int* in_sizes, int n_in,
                              void* d_out, int out_size)
{
    const float* u     = (const float*)d_in[0];
    const float* Lre   = (const float*)d_in[1];
    const float* Lim   = (const float*)d_in[2];
    const float* Bp    = (const float*)d_in[3];
    const float* Cp    = (const float*)d_in[4];
    const float* Dv    = (const float*)d_in[5];
    const float* lstep = (const float*)d_in[6];
    float* out = (float*)d_out;

    void *puh, *pw1, *pw2, *pxs;
    cudaGetSymbolAddress(&puh, g_uh);
    cudaGetSymbolAddress(&pw1, g_w1h);
    cudaGetSymbolAddress(&pw2, g_w2h);
    cudaGetSymbolAddress(&pxs, g_xsh);

    cudaFuncSetAttribute((const void*)gemm_mma<0>,
                         cudaFuncAttributeMaxDynamicSharedMemorySize, SMEM_SZ);
    cudaFuncSetAttribute((const void*)gemm_mma<1>,
                         cudaFuncAttributeMaxDynamicSharedMemorySize, SMEM_SZ);

    prep_lambda_kernel<<<2, 256>>>(Lre, Lim, lstep);          // 0 (zeroes flags)
    split_all_kernel<<<20480, 256>>>(u, Bp, Cp);               // 1 (u + W1 + W2)

    dim3 grid(1024 / 128, MTOT / 128);   // (8, 256)
    gemm_mma<0><<<grid, 256, SMEM_SZ>>>((const __half*)puh, (const __half*)pw1,
                                        nullptr, nullptr, nullptr);   // 2
    gemm_mma<1><<<grid, 256, SMEM_SZ>>>((const __half*)pxs, (const __half*)pw2,
                                        out, Dv, (const __half*)puh); // 3 <- profiled (GEMM2)
}

// round 17
// speedup vs baseline: 1.0840x; 1.0020x over previous
#include <cuda_runtime.h>
#include <cuda_fp16.h>
#include <math.h>
#include <stdint.h>

// ---------------- problem dims (fixed) ----------------
#define BSZ   8
#define LSEQ  4096
#define HDIM  1024
#define PDIM  512
#define MTOT  (BSZ * LSEQ)        // 32768
#define CHUNKL 128
#define NCHK  (LSEQ / CHUNKL)     // 32
#define NCHUNKS_TOT (BSZ * NCHK)  // 256

#define S1_SCALE 1024.0f          // power-of-2: all scale ops exact
#define S1_INV   (1.0f / 1024.0f)

// ---------------- device scratch ----------------
__device__ float2 g_lbc   [PDIM];               // lambda_bar
__device__ float2 g_lb32c [PDIM];               // lambda_bar^32
__device__ float2 g_lb128c[PDIM];               // lambda_bar^128
__device__ float  g_fac   [2 * PDIM];
__device__ __half g_uh  [(size_t)MTOT * 1024];
__device__ __half g_w1h [(size_t)1024 * 1024];  // rows interleaved: 2p=Re, 2p+1=Im (scaled 2^10)
__device__ __half g_w2h [(size_t)1024 * 1024];  // cols interleaved: 2p=C_re, 2p+1=-C_im
__device__ __half g_xsh [(size_t)MTOT * 1024];  // xs fp16, SCALED by 2^10 (unscaled in GEMM2 epi)
__device__ float2 g_cs2 [NCHUNKS_TOT * PDIM];   // per-chunk inclusive carries (scaled)
__device__ int    g_flag[NCHUNKS_TOT * 8];      // lookback ready flags (per by,bx)

// ---------------- PTX helpers ----------------
__device__ __forceinline__ uint32_t smem_u32(const void* p) {
    uint32_t a;
    asm("{ .reg .u64 t; cvta.to.shared.u64 t, %1; cvt.u32.u64 %0, t; }" : "=r"(a) : "l"(p));
    return a;
}
#define CP_ASYNC16(dst, src) \
    asm volatile("cp.async.cg.shared.global [%0], [%1], 16;" :: "r"(dst), "l"(src) : "memory")
#define CP_COMMIT() asm volatile("cp.async.commit_group;" ::: "memory")
#define CP_WAIT1()  asm volatile("cp.async.wait_group 1;" ::: "memory")

__device__ __forceinline__ void ldsm4(uint32_t* r, uint32_t addr) {
    asm volatile("ldmatrix.sync.aligned.m8n8.x4.shared.b16 {%0,%1,%2,%3}, [%4];"
                 : "=r"(r[0]), "=r"(r[1]), "=r"(r[2]), "=r"(r[3]) : "r"(addr));
}
__device__ __forceinline__ void mma16816(float* d, const uint32_t* a, uint32_t b0, uint32_t b1) {
    asm volatile("mma.sync.aligned.m16n8k16.row.col.f32.f16.f16.f32 "
                 "{%0,%1,%2,%3}, {%4,%5,%6,%7}, {%8,%9}, {%0,%1,%2,%3};"
                 : "+f"(d[0]), "+f"(d[1]), "+f"(d[2]), "+f"(d[3])
                 : "r"(a[0]), "r"(a[1]), "r"(a[2]), "r"(a[3]), "r"(b0), "r"(b1));
}
#define SWZ(x) ((x) ^ (((x) >> 3) & 0x70))

__device__ __forceinline__ float2 cmuladd(float2 a, float2 b, float2 c) {
    return make_float2(fmaf(a.x, b.x, fmaf(-a.y, b.y, c.x)),
                       fmaf(a.x, b.y, fmaf( a.y, b.x, c.y)));
}

// ---------------- param prep (also zeroes lookback flags) ----------------
__global__ void prep_lambda_kernel(const float* __restrict__ Lre,
                                   const float* __restrict__ Lim,
                                   const float* __restrict__ lstep)
{
    int t = blockIdx.x * blockDim.x + threadIdx.x;   // 0..511
    #pragma unroll
    for (int i = t; i < NCHUNKS_TOT * 8; i += 512) g_flag[i] = 0;

    int p = t;
    if (p >= PDIM) return;
    double lr = fmin((double)Lre[p], -1e-4);
    double li = (double)Lim[p];
    double s  = exp((double)lstep[p]);
    double er = exp(lr * s), th = li * s;
    double lbre = er * cos(th), lbim = er * sin(th);
    double den = lr * lr + li * li;
    double gre = lbre - 1.0, gim = lbim;
    g_lbc[p] = make_float2((float)lbre, (float)lbim);
    g_fac[p]        = (float)((gre * lr + gim * li) / den);
    g_fac[PDIM + p] = (float)((gim * lr - gre * li) / den);
    double er32 = exp(32.0 * lr * s), th32 = 32.0 * li * s;
    g_lb32c[p] = make_float2((float)(er32 * cos(th32)), (float)(er32 * sin(th32)));
    double er128 = exp(128.0 * lr * s), th128 = 128.0 * li * s;
    g_lb128c[p] = make_float2((float)(er128 * cos(th128)), (float)(er128 * sin(th128)));
}

// ---------------- merged split kernel: u (fp32->fp16), W1, W2 ----------------
__global__ void split_all_kernel(const float* __restrict__ u,
                                 const float* __restrict__ Bp,   // (P,H,2)
                                 const float* __restrict__ Cp)   // (H,P,2)
{
    int bid = blockIdx.x;
    if (bid < 16384) {
        size_t base = ((size_t)bid * 256 + threadIdx.x) * 8;
        float4 v0 = *(const float4*)(u + base);
        float4 v1 = *(const float4*)(u + base + 4);
        __half* o = g_uh + base;
        *(__half2*)(o)     = __floats2half2_rn(v0.x, v0.y);
        *(__half2*)(o + 2) = __floats2half2_rn(v0.z, v0.w);
        *(__half2*)(o + 4) = __floats2half2_rn(v1.x, v1.y);
        *(__half2*)(o + 6) = __floats2half2_rn(v1.z, v1.w);
    } else if (bid < 18432) {
        int idx = (bid - 16384) * 256 + threadIdx.x;
        int p = idx >> 10, h = idx & 1023;
        float b0 = Bp[p * 2048 + h * 2 + 0];
        float b1 = Bp[p * 2048 + h * 2 + 1];
        float fr = g_fac[p], fi = g_fac[PDIM + p];
        g_w1h[(size_t)(2 * p)     * 1024 + h] = __float2half_rn((fr * b0 - fi * b1) * S1_SCALE);
        g_w1h[(size_t)(2 * p + 1) * 1024 + h] = __float2half_rn((fr * b1 + fi * b0) * S1_SCALE);
    } else {
        int idx = (bid - 18432) * 256 + threadIdx.x;
        int h = idx >> 9, p = idx & 511;
        g_w2h[(size_t)h * 1024 + 2 * p]     = __float2half_rn( Cp[h * 1024 + p * 2 + 0]);
        g_w2h[(size_t)h * 1024 + 2 * p + 1] = __float2half_rn(-Cp[h * 1024 + p * 2 + 1]);
    }
}

// ---------------- HMMA fp16 GEMM: C = A(Mx1024) * B(1024x1024)^T ----
// 256 threads, 4x2 warp grid, 32x64 warp tile (proven optimum).
// MODE 0 (GEMM1): epilogue = fused scan (xs written SCALED, no unscale mults).
// MODE 1 (GEMM2): epilogue = (acc + D*2^10*u) * 2^-10, fp32 out. Exact folding.
#define STAGE_BYTES 32768
#define SMEM_SZ (3 * STAGE_BYTES)
#define NCH 16

__device__ __forceinline__ void load_chunk_async(
    const __half* __restrict__ A, const __half* __restrict__ B,
    int bm, int bn, int c, uint32_t sA, uint32_t sB, int tid)
{
    int col = c * 64;
    const char* Ag = (const char*)(A + (size_t)bm * 1024 + col);
    const char* Bg = (const char*)(B + (size_t)bn * 1024 + col);
    #pragma unroll
    for (int i = 0; i < 4; i++) {
        int idx = tid + (i << 8);
        int row = idx >> 3, ch = (idx & 7) << 4;
        CP_ASYNC16(sA + SWZ(row * 128 + ch), Ag + (size_t)row * 2048 + ch);
    }
    #pragma unroll
    for (int i = 0; i < 4; i++) {
        int idx = tid + (i << 8);
        int row = idx >> 3, ch = (idx & 7) << 4;
        CP_ASYNC16(sB + SWZ(row * 128 + ch), Bg + (size_t)row * 2048 + ch);
    }
}

template<int MODE>
__global__ void __launch_bounds__(256, 2)
gemm_mma(const __half* __restrict__ A, const __half* __restrict__ Bm,
         float* __restrict__ Cout, const float* __restrict__ Dv,
         const __half* __restrict__ Uh)
{
    extern __shared__ char smem[];
    const uint32_t sbase = smem_u32(smem);
    const int tid = threadIdx.x;
    const int lane = tid & 31, wid = tid >> 5;
    const int wm = wid & 3, wn = wid >> 2;   // 4 x 2 warp grid
    const int by = blockIdx.y;
    const int bq = by & 7;          // batch b  (MODE 0 k-major map)
    const int kq = by >> 3;         // chunk k
    const int bm = (MODE == 0) ? (bq * NCHK + kq) * 128 : by * 128;
    const int bn = blockIdx.x * 128;

    uint32_t sA[3], sB[3];
    #pragma unroll
    for (int s = 0; s < 3; s++) { sA[s] = sbase + s * STAGE_BYTES; sB[s] = sA[s] + 16384; }

    load_chunk_async(A, Bm, bm, bn, 0, sA[0], sB[0], tid); CP_COMMIT();
    load_chunk_async(A, Bm, bm, bn, 1, sA[1], sB[1], tid); CP_COMMIT();

    float acc[2][8][4];
    #pragma unroll
    for (int i = 0; i < 2; i++)
        #pragma unroll
        for (int j = 0; j < 8; j++)
            #pragma unroll
            for (int k = 0; k < 4; k++) acc[i][j][k] = 0.0f;

    const int arow = wm * 32 + (lane & 15);
    const int brow = wn * 64 + (lane & 15);
    const int khalf = (lane >> 4) * 16;

    #pragma unroll 1
    for (int c = 0; c < NCH; c++) {
        CP_WAIT1();
        __syncthreads();
        if (c + 2 < NCH)
            load_chunk_async(A, Bm, bm, bn, c + 2, sA[(c + 2) % 3], sB[(c + 2) % 3], tid);
        CP_COMMIT();

        const uint32_t a = sA[c % 3], b = sB[c % 3];
        #pragma unroll
        for (int ks = 0; ks < 4; ks++) {
            const int kb = ks * 32 + khalf;
            uint32_t af0[4], af1[4];
            ldsm4(af0, a + SWZ(arow * 128 + kb));
            ldsm4(af1, a + SWZ((arow + 16) * 128 + kb));
            #pragma unroll
            for (int np = 0; np < 4; np++) {
                uint32_t bf[4];
                ldsm4(bf, b + SWZ((brow + np * 16) * 128 + kb));
                mma16816(acc[0][np * 2 + 0], af0, bf[0], bf[2]);
                mma16816(acc[0][np * 2 + 1], af0, bf[1], bf[3]);
                mma16816(acc[1][np * 2 + 0], af1, bf[0], bf[2]);
                mma16816(acc[1][np * 2 + 1], af1, bf[1], bf[3]);
            }
        }
    }

    if (MODE == 1) {
        // epilogue: out = (acc + (D*2^10)*u) * 2^-10   (all folds exact, power of 2)
        #pragma unroll
        for (int mt = 0; mt < 2; mt++) {
            #pragma unroll
            for (int nt = 0; nt < 8; nt++) {
                const int row = bm + wm * 32 + mt * 16 + (lane >> 2);
                const int col = bn + wn * 64 + nt * 8 + (lane & 3) * 2;
                float d0 = acc[mt][nt][0], d1 = acc[mt][nt][1];
                float d2 = acc[mt][nt][2], d3 = acc[mt][nt][3];
                float2 dv = *(const float2*)(Dv + col);
                dv.x *= S1_SCALE; dv.y *= S1_SCALE;
                float2 u0 = __half22float2(*(const __half2*)(Uh + (size_t)row * 1024 + col));
                float2 u1 = __half22float2(*(const __half2*)(Uh + (size_t)(row + 8) * 1024 + col));
                d0 = fmaf(dv.x, u0.x, d0) * S1_INV; d1 = fmaf(dv.y, u0.y, d1) * S1_INV;
                d2 = fmaf(dv.x, u1.x, d2) * S1_INV; d3 = fmaf(dv.y, u1.y, d3) * S1_INV;
                *(float2*)(Cout + (size_t)row * 1024 + col)       = make_float2(d0, d1);
                *(float2*)(Cout + (size_t)(row + 8) * 1024 + col) = make_float2(d2, d3);
            }
        }
    } else {
        // fused scan: 4-quarter parallel local scan + decoupled lookback
        __syncthreads();
        float*  st = (float*)smem;                              // [128][130]
        float2* qs = (float2*)(smem + 128 * 130 * 4);           // [4][64] quarter sums
        float2* qc = (float2*)(smem + 128 * 130 * 4 + 2048);    // [4][64] quarter carry-ins
        #pragma unroll
        for (int mt = 0; mt < 2; mt++) {
            #pragma unroll
            for (int nt = 0; nt < 8; nt++) {
                const int row = wm * 32 + mt * 16 + (lane >> 2);
                const int col = wn * 64 + nt * 8 + (lane & 3) * 2;
                *(float2*)&st[row * 130 + col]       = make_float2(acc[mt][nt][0], acc[mt][nt][1]);
                *(float2*)&st[(row + 8) * 130 + col] = make_float2(acc[mt][nt][2], acc[mt][nt][3]);
            }
        }
        __syncthreads();
        // Phase A: 256 threads — zero-init local scan of a 32-step quarter
        {
            const int s  = tid & 63;
            const int jq = tid >> 6;
            const int p  = (bn >> 1) + s;
            const float2 lb = g_lbc[p];
            float2 x = make_float2(0.0f, 0.0f);
            float* base = &st[(jq * 32) * 130 + 2 * s];
            #pragma unroll 4
            for (int l = 0; l < 32; l++) {
                float2 v = *(float2*)(base + l * 130);
                x = cmuladd(lb, x, v);
                *(float2*)(base + l * 130) = x;
            }
            qs[jq * 64 + s] = x;
        }
        __syncthreads();
        // Phase B: 64 threads — combine, lookback, publish, derive carry-ins
        if (tid < 64) {
            const int s = tid;
            const int p = (bn >> 1) + s;
            const float2 l32  = g_lb32c[p];
            const float2 l128 = g_lb128c[p];
            float2 q0 = qs[s], q1 = qs[64 + s], q2 = qs[128 + s], q3 = qs[192 + s];
            float2 D1 = q0;
            float2 D2 = cmuladd(l32, D1, q1);
            float2 D3 = cmuladd(l32, D2, q2);
            float2 T  = cmuladd(l32, D3, q3);
            float2 cin = make_float2(0.0f, 0.0f);
            if (kq != 0) {
                volatile int* fl = (volatile int*)&g_flag[(by - 8) * 8 + blockIdx.x];
                while (*fl == 0) { }
                __threadfence();
                volatile float* cp = (volatile float*)&g_cs2[(size_t)(by - 8) * PDIM + p];
                cin.x = cp[0]; cin.y = cp[1];
            }
            g_cs2[(size_t)by * PDIM + p] = cmuladd(l128, cin, T);
            __threadfence();
            float2 C0 = cin;
            float2 C1 = cmuladd(l32, C0, q0);
            float2 C2 = cmuladd(l32, C1, q1);
            float2 C3 = cmuladd(l32, C2, q2);
            qc[s]       = C0;
            qc[64 + s]  = C1;
            qc[128 + s] = C2;
            qc[192 + s] = C3;
        }
        __syncthreads();
        if (tid == 0) *(volatile int*)&g_flag[by * 8 + blockIdx.x] = 1;
        // Phase C: 256 threads — apply correction, write fp16 xs (STAYS SCALED)
        {
            const int s  = tid & 63;
            const int jq = tid >> 6;
            const int p  = (bn >> 1) + s;
            const float2 lb = g_lbc[p];
            float2 cq = qc[jq * 64 + s];
            float2 g = make_float2(lb.x * cq.x - lb.y * cq.y,
                                   lb.x * cq.y + lb.y * cq.x);
            const float* base = &st[(jq * 32) * 130 + 2 * s];
            __half* xout = g_xsh + (size_t)(bm + jq * 32) * 1024 + bn + 2 * s;
            #pragma unroll 4
            for (int l = 0; l < 32; l++) {
                float2 v = *(const float2*)(base + l * 130);
                *(__half2*)(xout + (size_t)l * 1024) =
                    __floats2half2_rn(v.x + g.x, v.y + g.y);
                g = make_float2(lb.x * g.x - lb.y * g.y,
                                lb.x * g.y + lb.y * g.x);
            }
        }
    }
}

// ---------------- launcher ----------------
extern "C" void kernel_launch(void* const* d_in, const int* in_sizes, int n_in,
                              void* d_out, int out_size)
{
    const float* u     = (const float*)d_in[0];
    const float* Lre   = (const float*)d_in[1];
    const float* Lim   = (const float*)d_in[2];
    const float* Bp    = (const float*)d_in[3];
    const float* Cp    = (const float*)d_in[4];
    const float* Dv    = (const float*)d_in[5];
    const float* lstep = (const float*)d_in[6];
    float* out = (float*)d_out;

    void *puh, *pw1, *pw2, *pxs;
    cudaGetSymbolAddress(&puh, g_uh);
    cudaGetSymbolAddress(&pw1, g_w1h);
    cudaGetSymbolAddress(&pw2, g_w2h);
    cudaGetSymbolAddress(&pxs, g_xsh);

    cudaFuncSetAttribute((const void*)gemm_mma<0>,
                         cudaFuncAttributeMaxDynamicSharedMemorySize, SMEM_SZ);
    cudaFuncSetAttribute((const void*)gemm_mma<1>,
                         cudaFuncAttributeMaxDynamicSharedMemorySize, SMEM_SZ);

    prep_lambda_kernel<<<2, 256>>>(Lre, Lim, lstep);          // 0 (zeroes flags)
    split_all_kernel<<<20480, 256>>>(u, Bp, Cp);               // 1 (u + W1 + W2)

    dim3 grid(1024 / 128, MTOT / 128);   // (8, 256)
    gemm_mma<0><<<grid, 256, SMEM_SZ>>>((const __half*)puh, (const __half*)pw1,
                                        nullptr, nullptr, nullptr);   // 2
    gemm_mma<1><<<grid, 256, SMEM_SZ>>>((const __half*)pxs, (const __half*)pw2,
                                        out, Dv, (const __half*)puh); // 3 <- profiled (GEMM2)
}